// round 8
// baseline (speedup 1.0000x reference)
#include <cuda_runtime.h>
#include <cuda_bf16.h>
#include <cstdint>
#include <math.h>

#define N_INST 8192
#define DIM    2048
#define NC     256
#define ALPHA  7.18f
#define MINM   4

// ---------------- scratch (no allocs allowed) ----------------
__device__ float g_means [NC * DIM];            // [C][D] fp32 (for resid pass)
__device__ __nv_bfloat16 g_meansB[NC * DIM];    // [C][D] bf16 (GEMM B operand)
__device__ __nv_bfloat16 g_Xbf  [N_INST * DIM]; // bf16 X (GEMM A operand)
__device__ float g_mean_sq[NC];
__device__ float g_counts [NC];
__device__ int   g_valid  [NC];
__device__ float g_xsq  [N_INST];
__device__ float g_rnorm[N_INST];
__device__ float g_pd   [N_INST * 2];           // partial denoms (2 N-splits)
__device__ float g_stats[3];                    // [0]=stdev [1]=num_inst [2]=loss acc

__device__ __forceinline__ float fsqrt_approx(float x) {
    float y;
    asm("sqrt.approx.f32 %0, %1;" : "=f"(y) : "f"(x));
    return y;
}

__device__ __forceinline__ uint4 pack_bf16x8(float4 a, float4 b) {
    __nv_bfloat162 h0 = __floats2bfloat162_rn(a.x, a.y);
    __nv_bfloat162 h1 = __floats2bfloat162_rn(a.z, a.w);
    __nv_bfloat162 h2 = __floats2bfloat162_rn(b.x, b.y);
    __nv_bfloat162 h3 = __floats2bfloat162_rn(b.z, b.w);
    uint4 u;
    u.x = *(uint32_t*)&h0; u.y = *(uint32_t*)&h1;
    u.z = *(uint32_t*)&h2; u.w = *(uint32_t*)&h3;
    return u;
}

// ---------------- K1: per-cluster means + bf16 conversion of X ----------------
__global__ void __launch_bounds__(256) k_means(const float* __restrict__ X,
                                               const int* __restrict__ cl) {
    __shared__ int   sh_list[N_INST];
    __shared__ int   sh_cnt[256];
    __shared__ int   sh_off[256];
    __shared__ float red[256];

    const int c = blockIdx.x;
    const int t = threadIdx.x;
    const int CH = N_INST / 256;

    int base = t * CH;
    int cnt = 0;
    #pragma unroll 8
    for (int j = 0; j < CH; j++) cnt += (cl[base + j] == c);
    sh_cnt[t] = cnt;
    __syncthreads();
    if (t == 0) {
        int s = 0;
        for (int i = 0; i < 256; i++) { sh_off[i] = s; s += sh_cnt[i]; }
    }
    __syncthreads();
    int off = sh_off[t];
    for (int j = 0; j < CH; j++) {
        int idx = base + j;
        if (cl[idx] == c) sh_list[off++] = idx;
    }
    __syncthreads();
    const int total = sh_off[255] + sh_cnt[255];

    // thread t owns 8 contiguous cols [8t, 8t+8); float4 loads, uint4 bf16 stores
    const int col = t * 8;
    float4 s0 = {0,0,0,0}, s1 = {0,0,0,0};
    float4 q0 = {0,0,0,0}, q1 = {0,0,0,0};
    int m = 0;
    for (; m + 1 < total; m += 2) {
        int ra = sh_list[m], rb = sh_list[m + 1];
        const float4* rA = (const float4*)(X + (size_t)ra * DIM + col);
        const float4* rB = (const float4*)(X + (size_t)rb * DIM + col);
        float4 a0 = rA[0], a1 = rA[1];
        float4 b0 = rB[0], b1 = rB[1];
        s0.x += a0.x; s0.y += a0.y; s0.z += a0.z; s0.w += a0.w;
        s1.x += a1.x; s1.y += a1.y; s1.z += a1.z; s1.w += a1.w;
        q0.x += b0.x; q0.y += b0.y; q0.z += b0.z; q0.w += b0.w;
        q1.x += b1.x; q1.y += b1.y; q1.z += b1.z; q1.w += b1.w;
        ((uint4*)(g_Xbf + (size_t)ra * DIM))[t] = pack_bf16x8(a0, a1);
        ((uint4*)(g_Xbf + (size_t)rb * DIM))[t] = pack_bf16x8(b0, b1);
    }
    if (m < total) {
        int ra = sh_list[m];
        const float4* rA = (const float4*)(X + (size_t)ra * DIM + col);
        float4 a0 = rA[0], a1 = rA[1];
        s0.x += a0.x; s0.y += a0.y; s0.z += a0.z; s0.w += a0.w;
        s1.x += a1.x; s1.y += a1.y; s1.z += a1.z; s1.w += a1.w;
        ((uint4*)(g_Xbf + (size_t)ra * DIM))[t] = pack_bf16x8(a0, a1);
    }
    s0.x += q0.x; s0.y += q0.y; s0.z += q0.z; s0.w += q0.w;
    s1.x += q1.x; s1.y += q1.y; s1.z += q1.z; s1.w += q1.w;

    const float inv = 1.0f / fmaxf((float)total, 1.0f);
    float4 mu0, mu1;
    mu0.x = s0.x * inv; mu0.y = s0.y * inv; mu0.z = s0.z * inv; mu0.w = s0.w * inv;
    mu1.x = s1.x * inv; mu1.y = s1.y * inv; mu1.z = s1.z * inv; mu1.w = s1.w * inv;

    float4* mdst = (float4*)(g_means + (size_t)c * DIM + col);
    mdst[0] = mu0; mdst[1] = mu1;
    ((uint4*)(g_meansB + (size_t)c * DIM))[t] = pack_bf16x8(mu0, mu1);

    float msq = mu0.x*mu0.x + mu0.y*mu0.y + mu0.z*mu0.z + mu0.w*mu0.w
              + mu1.x*mu1.x + mu1.y*mu1.y + mu1.z*mu1.z + mu1.w*mu1.w;
    red[t] = msq;
    __syncthreads();
    for (int s = 128; s > 0; s >>= 1) {
        if (t < s) red[t] += red[t + s];
        __syncthreads();
    }
    if (t == 0) {
        g_mean_sq[c] = red[0];
        g_counts[c]  = (float)total;
        g_valid[c]   = (total >= MINM) ? 1 : 0;
    }
}

// ---------------- K2: warp-per-row xsq + residual norm from bf16 X ----------------
__global__ void __launch_bounds__(256) k_resid(const int* __restrict__ cl) {
    const int t = threadIdx.x;
    const int w = t >> 5;
    const int l = t & 31;
    const int i = blockIdx.x * 8 + w;
    const int c = cl[i];
    const uint4*  row = (const uint4*)(g_Xbf + (size_t)i * DIM);
    const float4* mu  = (const float4*)(g_means + (size_t)c * DIM);

    float sx = 0.0f, sr = 0.0f;
    #pragma unroll
    for (int j = 0; j < 8; j++) {
        int d8 = l + j * 32;
        uint4 v = row[d8];
        float4 m0 = mu[d8 * 2];
        float4 m1 = mu[d8 * 2 + 1];
        float2 x0 = __bfloat1622float2(*(const __nv_bfloat162*)&v.x);
        float2 x1 = __bfloat1622float2(*(const __nv_bfloat162*)&v.y);
        float2 x2 = __bfloat1622float2(*(const __nv_bfloat162*)&v.z);
        float2 x3 = __bfloat1622float2(*(const __nv_bfloat162*)&v.w);
        sx += x0.x*x0.x + x0.y*x0.y + x1.x*x1.x + x1.y*x1.y
            + x2.x*x2.x + x2.y*x2.y + x3.x*x3.x + x3.y*x3.y;
        float a0 = x0.x - m0.x, a1 = x0.y - m0.y, a2 = x1.x - m0.z, a3 = x1.y - m0.w;
        float a4 = x2.x - m1.x, a5 = x2.y - m1.y, a6 = x3.x - m1.z, a7 = x3.y - m1.w;
        sr += a0*a0 + a1*a1 + a2*a2 + a3*a3 + a4*a4 + a5*a5 + a6*a6 + a7*a7;
    }
    #pragma unroll
    for (int o = 16; o > 0; o >>= 1) {
        sx += __shfl_xor_sync(0xffffffffu, sx, o);
        sr += __shfl_xor_sync(0xffffffffu, sr, o);
    }
    if (l == 0) {
        g_xsq  [i] = sx;
        g_rnorm[i] = fsqrt_approx(sr);
    }
}

// ---------------- K3: global stats ----------------
__global__ void __launch_bounds__(256) k_stats(const int* __restrict__ cl) {
    __shared__ float red[256];
    __shared__ float s_ni;
    const int t = threadIdx.x;

    red[t] = g_valid[t] ? g_counts[t] : 0.0f;
    __syncthreads();
    for (int s = 128; s > 0; s >>= 1) {
        if (t < s) red[t] += red[t + s];
        __syncthreads();
    }
    if (t == 0) s_ni = red[0];
    __syncthreads();

    float sn = 0.0f;
    for (int i = t; i < N_INST; i += 256)
        sn += g_valid[cl[i]] ? g_rnorm[i] : 0.0f;
    red[t] = sn;
    __syncthreads();
    for (int s = 128; s > 0; s >>= 1) {
        if (t < s) red[t] += red[t + s];
        __syncthreads();
    }
    if (t == 0) {
        float s = red[0];
        g_stats[0] = (s * s) / s_ni;
        g_stats[1] = s_ni;
        g_stats[2] = 0.0f;
    }
}

// ---------------- K4: bf16 HMMA GEMM, N-split for occupancy ----------------
// Grid (128, 2): blockIdx.x = 64-row tile, blockIdx.y = 128-cluster split.
// 256 threads = 8 warps (2 M x 4 N). Warp tile 32x32. 2 CTAs/SM.
#define BM 64
#define BN 128
#define BK 16
#define PITCH 24
#define KT (DIM / BK)
#define STAGES 4

__device__ __forceinline__ void cp_async16(uint32_t dst, const void* src) {
    asm volatile("cp.async.cg.shared.global [%0], [%1], 16;" :: "r"(dst), "l"(src));
}
__device__ __forceinline__ void cp_commit() {
    asm volatile("cp.async.commit_group;");
}
__device__ __forceinline__ void cp_wait2() {
    asm volatile("cp.async.wait_group 2;");
}
__device__ __forceinline__ void ldsm4(uint32_t& r0, uint32_t& r1, uint32_t& r2,
                                      uint32_t& r3, uint32_t addr) {
    asm volatile("ldmatrix.sync.aligned.m8n8.x4.shared.b16 {%0,%1,%2,%3}, [%4];"
                 : "=r"(r0), "=r"(r1), "=r"(r2), "=r"(r3) : "r"(addr));
}
__device__ __forceinline__ void mma16816(float c[4], const uint32_t a[4],
                                         const uint32_t b[2]) {
    asm volatile(
        "mma.sync.aligned.m16n8k16.row.col.f32.bf16.bf16.f32 "
        "{%0,%1,%2,%3}, {%4,%5,%6,%7}, {%8,%9}, {%0,%1,%2,%3};"
        : "+f"(c[0]), "+f"(c[1]), "+f"(c[2]), "+f"(c[3])
        : "r"(a[0]), "r"(a[1]), "r"(a[2]), "r"(a[3]), "r"(b[0]), "r"(b[1]));
}

__global__ void __launch_bounds__(256, 2) k_gemm(const int* __restrict__ cl) {
    __shared__ __nv_bfloat16 sA[STAGES][BM * PITCH];   // 4*3072 B
    __shared__ __nv_bfloat16 sB[STAGES][BN * PITCH];   // 4*6144 B
    __shared__ float sdenom[BM][4];

    const int t    = threadIdx.x;
    const int wid  = t >> 5;
    const int l    = t & 31;
    const int wm   = wid >> 2;       // 0..1 : M
    const int wn   = wid & 3;        // 0..3 : N
    const int row0 = blockIdx.x * BM;
    const int nb   = blockIdx.y * BN;

    float acc[2][4][4];
    #pragma unroll
    for (int mt = 0; mt < 2; mt++)
        #pragma unroll
        for (int nt = 0; nt < 4; nt++)
            #pragma unroll
            for (int i = 0; i < 4; i++) acc[mt][nt][i] = 0.0f;

    // cp.async mappings: A 64 rows x 2 chunks (t<128); B 128 rows x 2 chunks (all)
    const int g_row = t >> 1;
    const int g_ch  = (t & 1) * 8;

    const __nv_bfloat16* Asrc = g_Xbf + (size_t)(row0 + g_row) * DIM + g_ch;
    const __nv_bfloat16* Bsrc = g_meansB + (size_t)(nb + g_row) * DIM + g_ch;

    uint32_t sA_base = (uint32_t)__cvta_generic_to_shared(&sA[0][0]);
    uint32_t sB_base = (uint32_t)__cvta_generic_to_shared(&sB[0][0]);
    uint32_t sA_dst  = sA_base + (g_row * PITCH + g_ch) * 2;
    uint32_t sB_dst  = sB_base + (g_row * PITCH + g_ch) * 2;
    const uint32_t stA = BM * PITCH * 2;
    const uint32_t stB = BN * PITCH * 2;

    // ldmatrix per-lane offsets
    uint32_t aoff[2];
    #pragma unroll
    for (int mt = 0; mt < 2; mt++)
        aoff[mt] = ((wm * 32 + mt * 16 + (l & 15)) * PITCH + (l >> 4) * 8) * 2;
    uint32_t boff[2];
    #pragma unroll
    for (int p = 0; p < 2; p++)
        boff[p] = ((wn * 32 + p * 16 + (l & 7) + ((l >> 4) & 1) * 8) * PITCH
                   + ((l >> 3) & 1) * 8) * 2;

    #pragma unroll
    for (int s = 0; s < 2; s++) {
        int kk = s * BK;
        if (t < 128) cp_async16(sA_dst + s * stA, Asrc + kk);
        cp_async16(sB_dst + s * stB, Bsrc + kk);
        cp_commit();
    }

    int s_cur = 0;
    for (int kt = 0; kt < KT; kt++) {
        if (kt + 2 < KT) {
            int s_nxt = (kt + 2) & (STAGES - 1);
            int kk = (kt + 2) * BK;
            if (t < 128) cp_async16(sA_dst + s_nxt * stA, Asrc + kk);
            cp_async16(sB_dst + s_nxt * stB, Bsrc + kk);
        }
        cp_commit();
        cp_wait2();
        __syncthreads();

        uint32_t sa = sA_base + s_cur * stA;
        uint32_t sb = sB_base + s_cur * stB;

        uint32_t a[2][4];
        ldsm4(a[0][0], a[0][1], a[0][2], a[0][3], sa + aoff[0]);
        ldsm4(a[1][0], a[1][1], a[1][2], a[1][3], sa + aoff[1]);

        #pragma unroll
        for (int p = 0; p < 2; p++) {
            uint32_t b0[2], b1[2];
            ldsm4(b0[0], b0[1], b1[0], b1[1], sb + boff[p]);
            mma16816(acc[0][2 * p],     a[0], b0);
            mma16816(acc[1][2 * p],     a[1], b0);
            mma16816(acc[0][2 * p + 1], a[0], b1);
            mma16816(acc[1][2 * p + 1], a[1], b1);
        }
        s_cur = (s_cur + 1) & (STAGES - 1);
    }

    // ---------------- epilogue: partial denominators for this split ----------------
    const float stdev = g_stats[0];
    const float sc = -0.5f / stdev;

    const int ar = l >> 2;
    const int ak2 = (l & 3) * 2;
    int rbase = row0 + wm * 32 + ar;
    float rxsq[4]; int rcl[4];
    #pragma unroll
    for (int v = 0; v < 4; v++) {
        int r = rbase + ((v & 1) * 8) + ((v >> 1) * 16);
        rxsq[v] = g_xsq[r];
        rcl[v]  = cl[r];
    }

    float p[4] = {0.f, 0.f, 0.f, 0.f};
    #pragma unroll
    for (int nt = 0; nt < 4; nt++) {
        int n0 = nb + wn * 32 + nt * 8 + ak2;
        float msq0 = g_mean_sq[n0], msq1 = g_mean_sq[n0 + 1];
        int v0 = g_valid[n0], v1 = g_valid[n0 + 1];
        #pragma unroll
        for (int mt = 0; mt < 2; mt++) {
            #pragma unroll
            for (int half = 0; half < 2; half++) {
                int vi = mt * 2 + half;
                float d2a = rxsq[vi] - 2.0f * acc[mt][nt][half * 2]     + msq0;
                float d2b = rxsq[vi] - 2.0f * acc[mt][nt][half * 2 + 1] + msq1;
                float da = fsqrt_approx(fmaxf(d2a, 0.0f));
                float db = fsqrt_approx(fmaxf(d2b, 0.0f));
                float ta = sc * da, tb = sc * db;
                float ea = 1.0f + fmaf(0.5f * ta, ta, ta);
                float eb = 1.0f + fmaf(0.5f * tb, tb, tb);
                if (v0 && n0     != rcl[vi]) p[vi] += ea;
                if (v1 && n0 + 1 != rcl[vi]) p[vi] += eb;
            }
        }
    }
    #pragma unroll
    for (int v = 0; v < 4; v++) {
        p[v] += __shfl_xor_sync(0xffffffffu, p[v], 1);
        p[v] += __shfl_xor_sync(0xffffffffu, p[v], 2);
    }
    if ((l & 3) == 0) {
        #pragma unroll
        for (int v = 0; v < 4; v++) {
            int lr = wm * 32 + ar + ((v & 1) * 8) + ((v >> 1) * 16);
            sdenom[lr][wn] = p[v];
        }
    }
    __syncthreads();

    if (t < BM) {
        float pd = sdenom[t][0] + sdenom[t][1] + sdenom[t][2] + sdenom[t][3];
        g_pd[(row0 + t) * 2 + blockIdx.y] = pd;
    }
}

// ---------------- K5: combine partial denoms -> loss terms ----------------
__global__ void __launch_bounds__(256) k_loss(const int* __restrict__ cl) {
    __shared__ float sred[8];
    const int t = threadIdx.x;
    const int r = blockIdx.x * 256 + t;
    const float stdev = g_stats[0];

    float denom = g_pd[r * 2] + g_pd[r * 2 + 1];
    int cr = cl[r];
    float term = 0.0f;
    if (g_valid[cr])
        term = logf(denom) + 0.5f * g_rnorm[r] / stdev + ALPHA;
    #pragma unroll
    for (int o = 16; o > 0; o >>= 1)
        term += __shfl_xor_sync(0xffffffffu, term, o);
    if ((t & 31) == 0) sred[t >> 5] = term;
    __syncthreads();
    if (t == 0) {
        float s = 0.0f;
        #pragma unroll
        for (int w = 0; w < 8; w++) s += sred[w];
        atomicAdd(&g_stats[2], s);
    }
}

// ---------------- K6: finalize ----------------
__global__ void k_final(float* __restrict__ out) {
    out[0] = g_stats[2] / g_stats[1];
}

// ---------------- launcher ----------------
extern "C" void kernel_launch(void* const* d_in, const int* in_sizes, int n_in,
                              void* d_out, int out_size) {
    const float* X  = (const float*)d_in[0];
    const int*   cl = (const int*)d_in[1];
    float* out = (float*)d_out;

    k_means<<<NC, 256>>>(X, cl);
    k_resid<<<N_INST / 8, 256>>>(cl);
    k_stats<<<1, 256>>>(cl);
    dim3 gg(N_INST / BM, 2);
    k_gemm<<<gg, 256>>>(cl);
    k_loss<<<N_INST / 256, 256>>>(cl);
    k_final<<<1, 1>>>(out);
}